// round 2
// baseline (speedup 1.0000x reference)
#include <cuda_runtime.h>
#include <cstdint>

// Problem constants (fixed shapes: B=8, H=W=512)
#define BB 8
#define NN (512*512)          // 262144 pixels per batch row
#define PP (BB*NN)
#define THREADS 256
#define TILE 2048             // pixels per block (2 groups of 4 per thread)
#define BLKX (NN/TILE)        // 128
#define EQCAP 4096

// ---------------- device scratch ----------------
__device__ uint32_t g_keys[PP];       // 8 MB
__device__ float    g_loss3[PP];      // 8 MB
__device__ uint32_t g_cand_key[PP];   // 8 MB (per-row region of NN)
__device__ uint32_t g_cand_idx[PP];   // 8 MB
__device__ int      g_ccount[BB];
__device__ uint32_t g_hist[BB*256];
__device__ uint32_t g_prefix[BB];
__device__ int      g_kneed[BB];
__device__ int      g_eqcount[BB];
__device__ int      g_eqlist[BB*EQCAP];
__device__ double   g_sum_l3;
__device__ unsigned long long g_sum_tsel;
__device__ unsigned long long g_ttotal;

__device__ __forceinline__ uint32_t f2mono(float f) {
    uint32_t u = __float_as_uint(f);
    return (u & 0x80000000u) ? ~u : (u | 0x80000000u);
}

// Robust scalar read (f32 vs f64 sniff; values are in (0,1)).
__device__ __forceinline__ double read_scalar(const void* p) {
    float f = *(const float*)p;
    if (f > 1e-6f && f < 1.0f) return (double)f;
    return *(const double*)p;
}

__device__ __forceinline__ void sm2(float x0, float x1,
                                    float& lp0, float& lp1, float& p0, float& p1) {
    float m  = fmaxf(x0, x1);
    float e0 = __expf(x0 - m);
    float e1 = __expf(x1 - m);
    float s  = e0 + e1;
    float ls = __logf(s);
    float r  = __fdividef(1.0f, s);
    lp0 = x0 - m - ls;
    lp1 = x1 - m - ls;
    p0  = e0 * r;
    p1  = e1 * r;
}

// per-pixel loss math (returns combined key-loss and loss3)
__device__ __forceinline__ void pixel_loss(float a1, float c1, float a2, float c2,
                                           float a3, float c3, int t,
                                           float kdw, float w,
                                           float& loss, float& l3) {
    float lp10, lp11, p10, p11; sm2(a1, c1, lp10, lp11, p10, p11);
    float lp20, lp21, p20, p21; sm2(a2, c2, lp20, lp21, p20, p21);
    float lp30, lp31, p30, p31; sm2(a3, c3, lp30, lp31, p30, p31);
    float tf = (float)t;
    float om11 = 1.0f - p11, om10 = 1.0f - p10;
    float om21 = 1.0f - p21, om20 = 1.0f - p20;
    float om31 = 1.0f - p31, om30 = 1.0f - p30;
    float l1 = -tf * om11*om11*lp11 - (1.0f-tf) * om10*om10*lp10;
    float l2 = -tf * om21*om21*lp21 - (1.0f-tf) * om20*om20*lp20;
    l3       = -tf * om31*om31*lp31 - (1.0f-tf) * om30*om30*lp30;
    float kdl12 = p10*(lp10-lp20) + p11*(lp11-lp21);
    float kdl21 = p20*(lp20-lp10) + p21*(lp21-lp11);
    loss = w * (l1 + l2 + l3) + kdw * (kdl12 + kdl21);
}

// ---------------- kernels ----------------

__global__ void k_init(const void* forget) {
    int tid = threadIdx.x;
    double rem = 1.0 - read_scalar(forget);
    int num_rem = (int)(rem * (double)NN);
    if (tid < BB) {
        g_kneed[tid]   = num_rem;
        g_prefix[tid]  = 0u;
        g_eqcount[tid] = 0;
        g_ccount[tid]  = 0;
    }
    if (tid == 0) { g_sum_l3 = 0.0; g_sum_tsel = 0ull; g_ttotal = 0ull; }
    for (int i = tid; i < BB*256; i += blockDim.x) g_hist[i] = 0u;
}

// Fused math + key/loss3 store + byte-3 histogram + target total.
__global__ void __launch_bounds__(THREADS)
k_compute(const float* __restrict__ in1, const float* __restrict__ in2,
          const float* __restrict__ in3, const int* __restrict__ tgt,
          const void* __restrict__ kdw_p)
{
    __shared__ uint32_t sh[256];
    int tid = threadIdx.x;
    sh[tid] = 0u;
    __syncthreads();

    const int row = blockIdx.y;
    const float kdw = (float)read_scalar(kdw_p);
    const float w   = 1.0f - kdw;

    const float4* b1a = (const float4*)(in1 + (size_t)row * 2 * NN);
    const float4* b1c = (const float4*)(in1 + (size_t)row * 2 * NN + NN);
    const float4* b2a = (const float4*)(in2 + (size_t)row * 2 * NN);
    const float4* b2c = (const float4*)(in2 + (size_t)row * 2 * NN + NN);
    const float4* b3a = (const float4*)(in3 + (size_t)row * 2 * NN);
    const float4* b3c = (const float4*)(in3 + (size_t)row * 2 * NN + NN);
    const int4*   bt  = (const int4*)(tgt + (size_t)row * NN);
    uint4*  kout = (uint4*)(g_keys  + (size_t)row * NN);
    float4* lout = (float4*)(g_loss3 + (size_t)row * NN);

    int tcnt = 0;

#pragma unroll
    for (int g = 0; g < 2; g++) {
        int vi = (blockIdx.x * TILE + g * (TILE/2)) / 4 + tid;  // float4 index
        float4 A1 = b1a[vi], C1 = b1c[vi];
        float4 A2 = b2a[vi], C2 = b2c[vi];
        float4 A3 = b3a[vi], C3 = b3c[vi];
        int4   T  = bt[vi];

        float ls0, ls1, ls2, ls3, l30, l31, l32, l33;
        pixel_loss(A1.x, C1.x, A2.x, C2.x, A3.x, C3.x, T.x, kdw, w, ls0, l30);
        pixel_loss(A1.y, C1.y, A2.y, C2.y, A3.y, C3.y, T.y, kdw, w, ls1, l31);
        pixel_loss(A1.z, C1.z, A2.z, C2.z, A3.z, C3.z, T.z, kdw, w, ls2, l32);
        pixel_loss(A1.w, C1.w, A2.w, C2.w, A3.w, C3.w, T.w, kdw, w, ls3, l33);

        uint4 K = make_uint4(f2mono(ls0), f2mono(ls1), f2mono(ls2), f2mono(ls3));
        kout[vi] = K;
        lout[vi] = make_float4(l30, l31, l32, l33);

        atomicAdd(&sh[K.x >> 24], 1u);
        atomicAdd(&sh[K.y >> 24], 1u);
        atomicAdd(&sh[K.z >> 24], 1u);
        atomicAdd(&sh[K.w >> 24], 1u);
        tcnt += T.x + T.y + T.z + T.w;
    }
    __syncthreads();
    if (sh[tid]) atomicAdd(&g_hist[row * 256 + tid], sh[tid]);

#pragma unroll
    for (int o = 16; o; o >>= 1) tcnt += __shfl_down_sync(0xffffffffu, tcnt, o);
    __shared__ int swt[8];
    if ((tid & 31) == 0) swt[tid >> 5] = tcnt;
    __syncthreads();
    if (tid == 0) {
        int s = 0;
#pragma unroll
        for (int i = 0; i < 8; i++) s += swt[i];
        atomicAdd(&g_ttotal, (unsigned long long)s);
    }
}

// One warp per row: find bucket containing the kneed-th element; zero hist.
__global__ void k_select(int shift) {
    int warp = threadIdx.x >> 5;
    int lane = threadIdx.x & 31;
    if (warp >= BB) return;
    int row = warp;
    unsigned kneed = (unsigned)g_kneed[row];

    unsigned cum = 0, cbefore = 0;
    int found_bin = -1;

#pragma unroll
    for (int c = 0; c < 8; c++) {
        unsigned v = g_hist[row * 256 + c * 32 + lane];
        unsigned s = v;
#pragma unroll
        for (int off = 1; off < 32; off <<= 1) {
            unsigned n = __shfl_up_sync(0xffffffffu, s, off);
            if (lane >= off) s += n;
        }
        unsigned total = __shfl_sync(0xffffffffu, s, 31);
        if (found_bin < 0) {
            unsigned mask = __ballot_sync(0xffffffffu, cum + s >= kneed);
            if (mask) {
                int fl = __ffs(mask) - 1;
                found_bin = c * 32 + fl;
                unsigned excl_fl = __shfl_sync(0xffffffffu, s - v, fl);
                cbefore = cum + excl_fl;
            }
        }
        cum += total;
        g_hist[row * 256 + c * 32 + lane] = 0u;
    }
    if (lane == 0) {
        g_prefix[row] |= ((uint32_t)found_bin) << shift;
        g_kneed[row]   = (int)(kneed - cbefore);
    }
}

// Warp-aggregated candidate append.
__device__ __forceinline__ int warp_append(bool pred, int* counter) {
    unsigned m = __ballot_sync(0xffffffffu, pred);
    int lane = threadIdx.x & 31;
    int base = 0;
    if (m) {
        int leader = __ffs(m) - 1;
        if (lane == leader) base = atomicAdd(counter, __popc(m));
        base = __shfl_sync(0xffffffffu, base, leader);
    }
    return base + __popc(m & ((1u << lane) - 1u));
}

// Single pass: accumulate sums for strictly-below-bin elements, compact
// in-bin candidates, build byte-2 histogram of candidates.
__global__ void __launch_bounds__(THREADS)
k_compact(const int* __restrict__ tgt) {
    __shared__ uint32_t sh[256];
    int tid = threadIdx.x;
    sh[tid] = 0u;
    __syncthreads();

    const int row = blockIdx.y;
    const uint32_t selbin = g_prefix[row] >> 24;
    const uint4*  keys = (const uint4*)(g_keys  + (size_t)row * NN);
    const float4* l3v  = (const float4*)(g_loss3 + (size_t)row * NN);
    const int4*   btv  = (const int4*)(tgt + (size_t)row * NN);
    uint32_t* ckey = g_cand_key + (size_t)row * NN;
    uint32_t* cidx = g_cand_idx + (size_t)row * NN;

    double sl = 0.0;
    int    st = 0;

#pragma unroll
    for (int g = 0; g < 2; g++) {
        int vi = (blockIdx.x * TILE + g * (TILE/2)) / 4 + tid;
        uint4  K = keys[vi];
        float4 L = l3v[vi];
        int4   T = btv[vi];
        uint32_t ks[4] = {K.x, K.y, K.z, K.w};
        float    ls[4] = {L.x, L.y, L.z, L.w};
        int      ts[4] = {T.x, T.y, T.z, T.w};
#pragma unroll
        for (int j = 0; j < 4; j++) {
            uint32_t b = ks[j] >> 24;
            bool below = (b < selbin);
            bool eq    = (b == selbin);
            if (below) { sl += (double)ls[j]; st += ts[j]; }
            int p = warp_append(eq, &g_ccount[row]);
            if (eq) {
                ckey[p] = ks[j];
                cidx[p] = (uint32_t)(vi * 4 + j);
                atomicAdd(&sh[(ks[j] >> 16) & 255u], 1u);
            }
        }
    }
    __syncthreads();
    if (sh[tid]) atomicAdd(&g_hist[row * 256 + tid], sh[tid]);

#pragma unroll
    for (int o = 16; o; o >>= 1) {
        sl += __shfl_down_sync(0xffffffffu, sl, o);
        st += __shfl_down_sync(0xffffffffu, st, o);
    }
    __shared__ double sd[8];
    __shared__ int    si[8];
    if ((tid & 31) == 0) { sd[tid >> 5] = sl; si[tid >> 5] = st; }
    __syncthreads();
    if (tid == 0) {
        double S = 0.0; int Ti = 0;
#pragma unroll
        for (int i = 0; i < 8; i++) { S += sd[i]; Ti += si[i]; }
        atomicAdd(&g_sum_l3, S);
        atomicAdd(&g_sum_tsel, (unsigned long long)Ti);
    }
}

// Histogram of candidates (lower bytes), filtered by higher-bit prefix match.
__global__ void __launch_bounds__(THREADS)
k_histc(int shift) {
    __shared__ uint32_t sh[256];
    int tid = threadIdx.x;
    sh[tid] = 0u;
    __syncthreads();

    int row = blockIdx.y;
    int cnt = g_ccount[row];
    uint32_t pfx = g_prefix[row] >> (shift + 8);
    const uint32_t* ckey = g_cand_key + (size_t)row * NN;

    for (int i = blockIdx.x * THREADS + tid; i < cnt; i += gridDim.x * THREADS) {
        uint32_t k = ckey[i];
        if ((k >> (shift + 8)) == pfx)
            atomicAdd(&sh[(k >> shift) & 255u], 1u);
    }
    __syncthreads();
    if (sh[tid]) atomicAdd(&g_hist[row * 256 + tid], sh[tid]);
}

// Sum selected candidates (< thr), collect ties (== thr).
__global__ void __launch_bounds__(THREADS)
k_sumc(const int* __restrict__ tgt) {
    int tid = threadIdx.x;
    int row = blockIdx.y;
    int cnt = g_ccount[row];
    uint32_t thr = g_prefix[row];
    const uint32_t* ckey = g_cand_key + (size_t)row * NN;
    const uint32_t* cidx = g_cand_idx + (size_t)row * NN;
    const float*    l3   = g_loss3 + (size_t)row * NN;
    const int*      bt   = tgt + (size_t)row * NN;

    double sl = 0.0;
    int    st = 0;
    for (int i = blockIdx.x * THREADS + tid; i < cnt; i += gridDim.x * THREADS) {
        uint32_t k = ckey[i];
        if (k < thr) {
            int idx = (int)cidx[i];
            sl += (double)l3[idx];
            st += bt[idx];
        } else if (k == thr) {
            int p = atomicAdd(&g_eqcount[row], 1);
            if (p < EQCAP) g_eqlist[row * EQCAP + p] = (int)cidx[i];
        }
    }
#pragma unroll
    for (int o = 16; o; o >>= 1) {
        sl += __shfl_down_sync(0xffffffffu, sl, o);
        st += __shfl_down_sync(0xffffffffu, st, o);
    }
    __shared__ double sd[8];
    __shared__ int    si[8];
    if ((tid & 31) == 0) { sd[tid >> 5] = sl; si[tid >> 5] = st; }
    __syncthreads();
    if (tid == 0) {
        double S = 0.0; int Ti = 0;
#pragma unroll
        for (int i = 0; i < 8; i++) { S += sd[i]; Ti += si[i]; }
        atomicAdd(&g_sum_l3, S);
        atomicAdd(&g_sum_tsel, (unsigned long long)Ti);
    }
}

// Resolve ties (stable: lowest original index first) and write outputs.
__global__ void k_final(const int* __restrict__ tgt, const void* __restrict__ forget,
                        float* __restrict__ out) {
    int tid = threadIdx.x;
    for (int row = 0; row < BB; row++) {
        int m = g_kneed[row];
        int c = min(g_eqcount[row], EQCAP);
        for (int j = tid; j < c; j += blockDim.x) {
            int idx = g_eqlist[row * EQCAP + j];
            int rank = 0;
            for (int q = 0; q < c; q++) rank += (g_eqlist[row * EQCAP + q] < idx) ? 1 : 0;
            if (rank < m) {
                atomicAdd(&g_sum_l3, (double)g_loss3[(size_t)row * NN + idx]);
                atomicAdd(&g_sum_tsel, (unsigned long long)tgt[(size_t)row * NN + idx]);
            }
        }
    }
    __threadfence();
    __syncthreads();
    if (tid == 0) {
        double sl = atomicAdd(&g_sum_l3, 0.0);
        unsigned long long ts = atomicAdd(&g_sum_tsel, 0ull);
        unsigned long long tt = atomicAdd(&g_ttotal, 0ull);
        double rem = 1.0 - read_scalar(forget);
        long long num_rem = (long long)(rem * (double)NN);
        double denom = (double)BB * (double)num_rem;
        out[0] = (float)(sl / denom);
        out[1] = (float)((double)ts / (double)tt);
    }
}

// ---------------- host entry ----------------
extern "C" void kernel_launch(void* const* d_in, const int* in_sizes, int n_in,
                              void* d_out, int out_size) {
    const float* in1    = (const float*)d_in[0];
    const float* in2    = (const float*)d_in[1];
    const float* in3    = (const float*)d_in[2];
    const int*   tgt    = (const int*)d_in[3];
    const void*  forget = d_in[4];
    const void*  kdw    = d_in[5];
    float* out = (float*)d_out;

    dim3 grid(BLKX, BB);
    dim3 gridc(16, BB);

    k_init<<<1, 256>>>(forget);
    k_compute<<<grid, THREADS>>>(in1, in2, in3, tgt, kdw);
    k_select<<<1, 256>>>(24);
    k_compact<<<grid, THREADS>>>(tgt);
    k_select<<<1, 256>>>(16);
    k_histc<<<gridc, THREADS>>>(8);
    k_select<<<1, 256>>>(8);
    k_histc<<<gridc, THREADS>>>(0);
    k_select<<<1, 256>>>(0);
    k_sumc<<<gridc, THREADS>>>(tgt);
    k_final<<<1, 256>>>(tgt, forget, out);

    (void)in_sizes; (void)n_in; (void)out_size;
}

// round 3
// speedup vs baseline: 2.5281x; 2.5281x over previous
#include <cuda_runtime.h>
#include <cstdint>

// Fixed shapes: B=8, H=W=512
#define BB 8
#define NN (512*512)          // 262144 pixels per row
#define PP (BB*NN)
#define THREADS 256
#define TILE 2048             // pixels per block
#define BLKX (NN/TILE)        // 128
#define EQCAP 4096
#define NB 2048               // max histogram bins

// ---------------- device scratch ----------------
__device__ uint32_t g_keys[PP];     // 8 MB
__device__ uint32_t g_pl3[PP];      // 8 MB  loss3 with target packed in sign bit
__device__ uint32_t g_hist[BB*NB];
__device__ uint32_t g_prefix[BB];
__device__ int      g_kneed[BB];
__device__ int      g_eqcount[BB];
__device__ int      g_eqlist[BB*EQCAP];
__device__ double   g_sum_l3;
__device__ unsigned long long g_sum_tsel;
__device__ unsigned long long g_ttotal;

__device__ __forceinline__ uint32_t f2mono(float f) {
    uint32_t u = __float_as_uint(f);
    return (u & 0x80000000u) ? ~u : (u | 0x80000000u);
}

// Robust scalar read (f32 vs f64 sniff; true values are in (0,1)).
__device__ __forceinline__ double read_scalar(const void* p) {
    float f = *(const float*)p;
    if (f > 1e-6f && f < 1.0f) return (double)f;
    return *(const double*)p;
}

// 2-class log-softmax: 3 MUFU ops (exp, rcp, log).
// d = x0-x1; t = e^{-d}; p0 = 1/(1+t); p1 = t*p0; lp0 = log(p0); lp1 = lp0 - d.
__device__ __forceinline__ void sm2(float x0, float x1,
                                    float& lp0, float& lp1, float& p0, float& p1) {
    float d = x0 - x1;
    float t = __expf(fminf(-d, 80.0f));
    p0 = __fdividef(1.0f, 1.0f + t);
    p1 = t * p0;
    lp0 = __logf(p0);
    lp1 = lp0 - d;
}

__device__ __forceinline__ void pixel_loss(float a1, float c1, float a2, float c2,
                                           float a3, float c3, int t,
                                           float kdw, float w,
                                           float& loss, float& l3) {
    float lp10, lp11, p10, p11; sm2(a1, c1, lp10, lp11, p10, p11);
    float lp20, lp21, p20, p21; sm2(a2, c2, lp20, lp21, p20, p21);
    float lp30, lp31, p30, p31; sm2(a3, c3, lp30, lp31, p30, p31);
    float tf = (float)t;
    float om11 = 1.0f - p11, om10 = 1.0f - p10;
    float om21 = 1.0f - p21, om20 = 1.0f - p20;
    float om31 = 1.0f - p31, om30 = 1.0f - p30;
    float l1 = -tf * om11*om11*lp11 - (1.0f-tf) * om10*om10*lp10;
    float l2 = -tf * om21*om21*lp21 - (1.0f-tf) * om20*om20*lp20;
    l3       = -tf * om31*om31*lp31 - (1.0f-tf) * om30*om30*lp30;
    float kdl12 = p10*(lp10-lp20) + p11*(lp11-lp21);
    float kdl21 = p20*(lp20-lp10) + p21*(lp21-lp11);
    loss = w * (l1 + l2 + l3) + kdw * (kdl12 + kdl21);
}

// ---------------- kernels ----------------

__global__ void k_init(const void* forget) {
    int tid = threadIdx.x + blockIdx.x * blockDim.x;
    if (blockIdx.x == 0) {
        double rem = 1.0 - read_scalar(forget);
        int num_rem = (int)(rem * (double)NN);
        if (threadIdx.x < BB) {
            g_kneed[threadIdx.x]   = num_rem;
            g_prefix[threadIdx.x]  = 0u;
            g_eqcount[threadIdx.x] = 0;
        }
        if (threadIdx.x == 0) { g_sum_l3 = 0.0; g_sum_tsel = 0ull; g_ttotal = 0ull; }
    }
    for (int i = tid; i < BB*NB; i += gridDim.x * blockDim.x) g_hist[i] = 0u;
}

// Fused math + key/payload store + 2048-bin histogram (top 11 bits) + target total.
__global__ void __launch_bounds__(THREADS)
k_compute(const float* __restrict__ in1, const float* __restrict__ in2,
          const float* __restrict__ in3, const int* __restrict__ tgt,
          const void* __restrict__ kdw_p)
{
    __shared__ uint32_t sh[NB];
    int tid = threadIdx.x;
#pragma unroll
    for (int i = 0; i < NB/THREADS; i++) sh[tid + i*THREADS] = 0u;
    __syncthreads();

    const int row = blockIdx.y;
    const float kdw = (float)read_scalar(kdw_p);
    const float w   = 1.0f - kdw;

    const float4* b1a = (const float4*)(in1 + (size_t)row * 2 * NN);
    const float4* b1c = (const float4*)(in1 + (size_t)row * 2 * NN + NN);
    const float4* b2a = (const float4*)(in2 + (size_t)row * 2 * NN);
    const float4* b2c = (const float4*)(in2 + (size_t)row * 2 * NN + NN);
    const float4* b3a = (const float4*)(in3 + (size_t)row * 2 * NN);
    const float4* b3c = (const float4*)(in3 + (size_t)row * 2 * NN + NN);
    const int4*   bt  = (const int4*)(tgt + (size_t)row * NN);
    uint4* kout = (uint4*)(g_keys + (size_t)row * NN);
    uint4* pout = (uint4*)(g_pl3  + (size_t)row * NN);

    int tcnt = 0;

#pragma unroll
    for (int g = 0; g < 2; g++) {
        int vi = (blockIdx.x * TILE + g * (TILE/2)) / 4 + tid;
        float4 A1 = b1a[vi], C1 = b1c[vi];
        float4 A2 = b2a[vi], C2 = b2c[vi];
        float4 A3 = b3a[vi], C3 = b3c[vi];
        int4   T  = bt[vi];

        float ls0, ls1, ls2, ls3, l30, l31, l32, l33;
        pixel_loss(A1.x, C1.x, A2.x, C2.x, A3.x, C3.x, T.x, kdw, w, ls0, l30);
        pixel_loss(A1.y, C1.y, A2.y, C2.y, A3.y, C3.y, T.y, kdw, w, ls1, l31);
        pixel_loss(A1.z, C1.z, A2.z, C2.z, A3.z, C3.z, T.z, kdw, w, ls2, l32);
        pixel_loss(A1.w, C1.w, A2.w, C2.w, A3.w, C3.w, T.w, kdw, w, ls3, l33);

        uint4 K = make_uint4(f2mono(ls0), f2mono(ls1), f2mono(ls2), f2mono(ls3));
        kout[vi] = K;
        uint4 P = make_uint4(__float_as_uint(l30) | ((uint32_t)T.x << 31),
                             __float_as_uint(l31) | ((uint32_t)T.y << 31),
                             __float_as_uint(l32) | ((uint32_t)T.z << 31),
                             __float_as_uint(l33) | ((uint32_t)T.w << 31));
        pout[vi] = P;

        atomicAdd(&sh[K.x >> 21], 1u);
        atomicAdd(&sh[K.y >> 21], 1u);
        atomicAdd(&sh[K.z >> 21], 1u);
        atomicAdd(&sh[K.w >> 21], 1u);
        tcnt += T.x + T.y + T.z + T.w;
    }
    __syncthreads();
#pragma unroll
    for (int i = 0; i < NB/THREADS; i++) {
        uint32_t v = sh[tid + i*THREADS];
        if (v) atomicAdd(&g_hist[row * NB + tid + i*THREADS], v);
    }

#pragma unroll
    for (int o = 16; o; o >>= 1) tcnt += __shfl_down_sync(0xffffffffu, tcnt, o);
    __shared__ int swt[8];
    if ((tid & 31) == 0) swt[tid >> 5] = tcnt;
    __syncthreads();
    if (tid == 0) {
        int s = 0;
#pragma unroll
        for (int i = 0; i < 8; i++) s += swt[i];
        atomicAdd(&g_ttotal, (unsigned long long)s);
    }
}

// One block per row: find the bin containing the kneed-th element among nbins,
// update prefix/kneed, zero the hist region for the next pass.
__global__ void k_select(int nbins, int shift) {
    int row = blockIdx.x;
    int tid = threadIdx.x;
    int per = nbins >> 8;                 // bins per thread (8 or 4)
    uint32_t* h = g_hist + row * NB;
    unsigned kneed = (unsigned)g_kneed[row];

    unsigned local[8];
    unsigned lsum = 0;
    for (int i = 0; i < per; i++) { local[i] = h[tid * per + i]; lsum += local[i]; }

    __shared__ unsigned ss[256];
    ss[tid] = lsum;
    __syncthreads();
    // inclusive Hillis-Steele scan
    for (int off = 1; off < 256; off <<= 1) {
        unsigned n = (tid >= off) ? ss[tid - off] : 0u;
        __syncthreads();
        ss[tid] += n;
        __syncthreads();
    }
    unsigned incl = ss[tid];
    unsigned excl = incl - lsum;

    if (excl < kneed && kneed <= incl) {
        unsigned cum = excl;
        for (int i = 0; i < per; i++) {
            if (cum + local[i] >= kneed) {
                g_prefix[row] |= ((uint32_t)(tid * per + i)) << shift;
                g_kneed[row]   = (int)(kneed - cum);
                break;
            }
            cum += local[i];
        }
    }
    for (int i = 0; i < per; i++) h[tid * per + i] = 0u;
}

// Histogram of an 11/10-bit digit, filtered by higher-bit prefix. Vectorized.
__global__ void __launch_bounds__(THREADS)
k_hist(int shift, int digbits) {
    __shared__ uint32_t sh[NB];
    int tid = threadIdx.x;
#pragma unroll
    for (int i = 0; i < NB/THREADS; i++) sh[tid + i*THREADS] = 0u;
    __syncthreads();

    int row = blockIdx.y;
    int hs = shift + digbits;
    uint32_t pfx = g_prefix[row] >> hs;
    uint32_t mask = (1u << digbits) - 1u;
    const uint4* keys = (const uint4*)(g_keys + (size_t)row * NN);

    int vi = blockIdx.x * (TILE/4) + tid;
    uint4 K0 = keys[vi];
    uint4 K1 = keys[vi + THREADS];

    uint32_t ks[8] = {K0.x, K0.y, K0.z, K0.w, K1.x, K1.y, K1.z, K1.w};
#pragma unroll
    for (int j = 0; j < 8; j++)
        if ((ks[j] >> hs) == pfx)
            atomicAdd(&sh[(ks[j] >> shift) & mask], 1u);

    __syncthreads();
#pragma unroll
    for (int i = 0; i < NB/THREADS; i++) {
        uint32_t v = sh[tid + i*THREADS];
        if (v) atomicAdd(&g_hist[row * NB + tid + i*THREADS], v);
    }
}

// Sum loss3/targets for keys < thr, collect ties (== thr). Vectorized.
__global__ void __launch_bounds__(THREADS)
k_sum() {
    int tid = threadIdx.x;
    int row = blockIdx.y;
    uint32_t thr = g_prefix[row];
    const uint4* keys = (const uint4*)(g_keys + (size_t)row * NN);
    const uint4* pl3  = (const uint4*)(g_pl3  + (size_t)row * NN);

    int vi = blockIdx.x * (TILE/4) + tid;
    uint4 K0 = keys[vi];
    uint4 K1 = keys[vi + THREADS];
    uint4 P0 = pl3[vi];
    uint4 P1 = pl3[vi + THREADS];

    uint32_t ks[8] = {K0.x, K0.y, K0.z, K0.w, K1.x, K1.y, K1.z, K1.w};
    uint32_t ps[8] = {P0.x, P0.y, P0.z, P0.w, P1.x, P1.y, P1.z, P1.w};

    float sl = 0.0f;   // per-thread partial in f32 (≤8 adds), promoted below
    int   st = 0;
#pragma unroll
    for (int j = 0; j < 8; j++) {
        if (ks[j] < thr) {
            sl += __uint_as_float(ps[j] & 0x7fffffffu);
            st += (int)(ps[j] >> 31);
        } else if (ks[j] == thr) {
            int p = atomicAdd(&g_eqcount[row], 1);
            if (p < EQCAP) g_eqlist[row * EQCAP + p] = vi * 4 + (j < 4 ? j : THREADS*4 + j - 4);
        }
    }
    double sld = (double)sl;
#pragma unroll
    for (int o = 16; o; o >>= 1) {
        sld += __shfl_down_sync(0xffffffffu, sld, o);
        st  += __shfl_down_sync(0xffffffffu, st, o);
    }
    __shared__ double sd[8];
    __shared__ int    si[8];
    if ((tid & 31) == 0) { sd[tid >> 5] = sld; si[tid >> 5] = st; }
    __syncthreads();
    if (tid == 0) {
        double S = 0.0; int Ti = 0;
#pragma unroll
        for (int i = 0; i < 8; i++) { S += sd[i]; Ti += si[i]; }
        atomicAdd(&g_sum_l3, S);
        atomicAdd(&g_sum_tsel, (unsigned long long)Ti);
    }
}

// Resolve ties (stable: lowest original index) and write outputs.
__global__ void k_final(const void* __restrict__ forget, float* __restrict__ out) {
    int tid = threadIdx.x;
    for (int row = 0; row < BB; row++) {
        int m = g_kneed[row];
        int c = min(g_eqcount[row], EQCAP);
        for (int j = tid; j < c; j += blockDim.x) {
            int idx = g_eqlist[row * EQCAP + j];
            int rank = 0;
            for (int q = 0; q < c; q++) rank += (g_eqlist[row * EQCAP + q] < idx) ? 1 : 0;
            if (rank < m) {
                uint32_t p = g_pl3[(size_t)row * NN + idx];
                atomicAdd(&g_sum_l3, (double)__uint_as_float(p & 0x7fffffffu));
                atomicAdd(&g_sum_tsel, (unsigned long long)(p >> 31));
            }
        }
    }
    __threadfence();
    __syncthreads();
    if (tid == 0) {
        double sl = atomicAdd(&g_sum_l3, 0.0);
        unsigned long long ts = atomicAdd(&g_sum_tsel, 0ull);
        unsigned long long tt = atomicAdd(&g_ttotal, 0ull);
        double rem = 1.0 - read_scalar(forget);
        long long num_rem = (long long)(rem * (double)NN);
        double denom = (double)BB * (double)num_rem;
        out[0] = (float)(sl / denom);
        out[1] = (float)((double)ts / (double)tt);
    }
}

// ---------------- host entry ----------------
extern "C" void kernel_launch(void* const* d_in, const int* in_sizes, int n_in,
                              void* d_out, int out_size) {
    const float* in1    = (const float*)d_in[0];
    const float* in2    = (const float*)d_in[1];
    const float* in3    = (const float*)d_in[2];
    const int*   tgt    = (const int*)d_in[3];
    const void*  forget = d_in[4];
    const void*  kdw    = d_in[5];
    float* out = (float*)d_out;

    dim3 grid(BLKX, BB);

    k_init<<<16, 256>>>(forget);
    k_compute<<<grid, THREADS>>>(in1, in2, in3, tgt, kdw);
    k_select<<<BB, 256>>>(2048, 21);   // digit A: bits [21,32)
    k_hist<<<grid, THREADS>>>(10, 11); // digit B: bits [10,21)
    k_select<<<BB, 256>>>(2048, 10);
    k_hist<<<grid, THREADS>>>(0, 10);  // digit C: bits [0,10)
    k_select<<<BB, 256>>>(1024, 0);
    k_sum<<<grid, THREADS>>>();
    k_final<<<1, 256>>>(forget, out);

    (void)in_sizes; (void)n_in; (void)out_size;
}